// round 10
// baseline (speedup 1.0000x reference)
#include <cuda_runtime.h>
#include <cuda_bf16.h>
#include <cstdint>

// Problem constants
#define BB   256
#define LL   50
#define DD   128
#define KK   4
#define VV   50000
#define VM1  49999
#define BL   (BB*LL)        // 12800
#define LEN_OPT 5
#define BETA_S 0.01f
#define EPS_N  1e-12f

// Arch-specific (sm_103a) feature gate
#if defined(__CUDA_ARCH__)
#  if defined(__CUDA_ARCH_FEAT_SM103_ALL) || defined(__CUDA_ARCH_FEAT_SM100_ALL) || \
      defined(__CUDA_ARCH_FEAT_SM101_ALL) || \
      (defined(__CUDA_ARCH_SPECIFIC__) && (__CUDA_ARCH_SPECIFIC__ >= 1000)) || \
      (defined(__CUDA_ARCH_FAMILY_SPECIFIC__) && (__CUDA_ARCH_FAMILY_SPECIFIC__ >= 1000))
#    define HAS_TCGEN05 1
#  else
#    define HAS_TCGEN05 0
#  endif
#else
#  define HAS_TCGEN05 0
#endif

// ---------------- scratch (static device globals; no allocation) ----------------
__device__ float g_hsw1 [BB*DD];
__device__ float g_lens [BB];
__device__ float g_posw1[50*DD];
__device__ float g_beta [BL*KK];
__device__ __align__(16) __nv_bfloat16 g_sel_hi[BB*KK*DD];
__device__ __align__(16) __nv_bfloat16 g_sel_lo[BB*KK*DD];
__device__ __align__(16) __nv_bfloat16 g_emb_hi[(size_t)VM1*DD];
__device__ __align__(16) __nv_bfloat16 g_emb_lo[(size_t)VM1*DD];
__device__ __align__(16) __nv_bfloat16 g_w1b_hi[128*256],  g_w1b_lo[128*256];
__device__ __align__(16) __nv_bfloat16 g_glub_hi[512*128], g_glub_lo[512*128];
__device__ __align__(16) __nv_bfloat16 g_aw2b_hi[128*128], g_aw2b_lo[128*128];

__device__ __forceinline__ float sigmoidf(float x){ return 1.0f/(1.0f+expf(-x)); }

__device__ __forceinline__ uint32_t smem_u32(const void* p) {
    uint32_t a;
    asm("{ .reg .u64 t; cvta.to.shared.u64 t, %1; cvt.u32.u64 %0, t; }" : "=r"(a) : "l"(p));
    return a;
}
#define SWZ128(x) ((x) ^ (((x) >> 3) & 0x70))

static constexpr uint64_t SMEM_DESC_BASE_SW128 =
    (uint64_t(2) << 61) | (uint64_t(1) << 46) | (uint64_t(64) << 32) | (uint64_t(1) << 16);
#define MAKE_DESC(addr) (SMEM_DESC_BASE_SW128 | ((uint64_t)((addr) >> 4) & 0x3FFF))

#if HAS_TCGEN05
__device__ __forceinline__ uint32_t elect1() {
    uint32_t p;
    asm volatile("{ .reg .pred p; elect.sync _|p, 0xFFFFFFFF; selp.b32 %0,1,0,p; }" : "=r"(p));
    return p;
}
__device__ __forceinline__ void mma_f16_ss(uint32_t d_tmem, uint64_t a_desc,
                                           uint64_t b_desc, uint32_t idesc, int en)
{
    asm volatile(
        "{\n\t.reg .pred p;\n\t"
        "setp.ne.u32 p, %4, 0;\n\t"
        "tcgen05.mma.cta_group::1.kind::f16 [%0], %1, %2, %3, {%5,%5,%5,%5}, p;\n\t}"
        :: "r"(d_tmem), "l"(a_desc), "l"(b_desc), "r"(idesc), "r"(en), "r"(0u)
        : "memory");
}
__device__ __forceinline__ void mma_f16_ts(uint32_t d_tmem, uint32_t a_tmem,
                                           uint64_t b_desc, uint32_t idesc, int en)
{
    asm volatile(
        "{\n\t.reg .pred p;\n\t"
        "setp.ne.u32 p, %4, 0;\n\t"
        "tcgen05.mma.cta_group::1.kind::f16 [%0], [%1], %2, %3, {%5,%5,%5,%5}, p;\n\t}"
        :: "r"(d_tmem), "r"(a_tmem), "l"(b_desc), "r"(idesc), "r"(en), "r"(0u)
        : "memory");
}
__device__ __forceinline__ void cp16(uint32_t dst, const void* src) {
    asm volatile("cp.async.cg.shared.global [%0], [%1], 16;" :: "r"(dst), "l"(src));
}
__device__ __forceinline__ void cp_commit() { asm volatile("cp.async.commit_group;" ::: "memory"); }
__device__ __forceinline__ void cp_wait0()  { asm volatile("cp.async.wait_group 0;" ::: "memory"); }
__device__ __forceinline__ void cp_wait1()  { asm volatile("cp.async.wait_group 1;" ::: "memory"); }
#define MBAR_WAIT(mbar, par) do {                                              \
    asm volatile(                                                              \
        "{\n\t.reg .pred P1;\n\t"                                              \
        "WL_%=:\n\t"                                                           \
        "mbarrier.try_wait.parity.acquire.cta.shared::cta.b64 P1, [%0], %1, 0x989680;\n\t" \
        "@P1 bra.uni WD_%=;\n\t"                                               \
        "bra.uni WL_%=;\n\t"                                                   \
        "WD_%=:\n\t}" :: "r"(mbar), "r"(par) : "memory");                      \
} while(0)
#define TCOMMIT(mbar)                                                          \
    asm volatile(                                                              \
        "tcgen05.commit.cta_group::1.mbarrier::arrive::one.shared::cluster.b64 [%0];" \
        :: "r"(mbar) : "memory")
#define LDTM32(r, addr)                                                        \
    asm volatile(                                                              \
        "tcgen05.ld.sync.aligned.32x32b.x32.b32 "                              \
        "{%0,%1,%2,%3,%4,%5,%6,%7,%8,%9,%10,%11,%12,%13,%14,%15,"              \
        "%16,%17,%18,%19,%20,%21,%22,%23,%24,%25,%26,%27,%28,%29,%30,%31}, [%32];" \
        : "=r"(r[0]),"=r"(r[1]),"=r"(r[2]),"=r"(r[3]),"=r"(r[4]),"=r"(r[5]),"=r"(r[6]),"=r"(r[7]), \
          "=r"(r[8]),"=r"(r[9]),"=r"(r[10]),"=r"(r[11]),"=r"(r[12]),"=r"(r[13]),"=r"(r[14]),"=r"(r[15]), \
          "=r"(r[16]),"=r"(r[17]),"=r"(r[18]),"=r"(r[19]),"=r"(r[20]),"=r"(r[21]),"=r"(r[22]),"=r"(r[23]), \
          "=r"(r[24]),"=r"(r[25]),"=r"(r[26]),"=r"(r[27]),"=r"(r[28]),"=r"(r[29]),"=r"(r[30]),"=r"(r[31]) \
        : "r"(addr))
#define STTM32(addr, r)                                                        \
    asm volatile(                                                              \
        "tcgen05.st.sync.aligned.32x32b.x32.b32 [%0], "                        \
        "{%1,%2,%3,%4,%5,%6,%7,%8,%9,%10,%11,%12,%13,%14,%15,%16,"             \
        "%17,%18,%19,%20,%21,%22,%23,%24,%25,%26,%27,%28,%29,%30,%31,%32};"    \
        :: "r"(addr),                                                          \
           "r"(r[0]),"r"(r[1]),"r"(r[2]),"r"(r[3]),"r"(r[4]),"r"(r[5]),"r"(r[6]),"r"(r[7]), \
           "r"(r[8]),"r"(r[9]),"r"(r[10]),"r"(r[11]),"r"(r[12]),"r"(r[13]),"r"(r[14]),"r"(r[15]), \
           "r"(r[16]),"r"(r[17]),"r"(r[18]),"r"(r[19]),"r"(r[20]),"r"(r[21]),"r"(r[22]),"r"(r[23]), \
           "r"(r[24]),"r"(r[25]),"r"(r[26]),"r"(r[27]),"r"(r[28]),"r"(r[29]),"r"(r[30]),"r"(r[31]) \
        : "memory")
#endif

__device__ __forceinline__ ushort bf_hi_us(float v, float& rem) {
    __nv_bfloat16 hb = __float2bfloat16(v);
    rem = v - __bfloat162float(hb);
    return *reinterpret_cast<ushort*>(&hb);
}
__device__ __forceinline__ ushort bf_us(float v) {
    __nv_bfloat16 b = __float2bfloat16(v);
    return *reinterpret_cast<ushort*>(&b);
}

// ---------------- prep A: emb normalize + hi/lo split (side stream) ----------------
__global__ void k_prep_emb(const float* __restrict__ emb)
{
    int w = threadIdx.x >> 5, lane = threadIdx.x & 31;
    int v = blockIdx.x*8 + w;
    if (v >= VM1) return;
    float4 x = *(const float4*)(emb + (size_t)(1 + v)*DD + lane*4);
    float s = x.x*x.x + x.y*x.y + x.z*x.z + x.w*x.w;
    #pragma unroll
    for (int o = 16; o > 0; o >>= 1) s += __shfl_xor_sync(0xffffffffu, s, o);
    float inv = 1.0f / fmaxf(sqrtf(s), EPS_N);
    float n[4] = {x.x*inv, x.y*inv, x.z*inv, x.w*inv};
    __nv_bfloat16 hi[4], lo[4];
    #pragma unroll
    for (int i = 0; i < 4; i++) {
        hi[i] = __float2bfloat16(n[i]);
        lo[i] = __float2bfloat16(n[i] - __bfloat162float(hi[i]));
    }
    *(uint64_t*)(&g_emb_hi[(size_t)v*DD + lane*4]) = *(uint64_t*)hi;
    *(uint64_t*)(&g_emb_lo[(size_t)v*DD + lane*4]) = *(uint64_t*)lo;
}

// ---------------- prep B: weights + posw1 + hs (main stream) -----------------------
// blocks [0,448): weight transpose+split; [448,498): posw1; [498,754): hs/lens/hsw1
#define PR_PW 448
#define PR_HS 498
#define PR_GRID 754
__global__ void k_prep_rest(const float* __restrict__ w1, const float* __restrict__ glu1_w,
                            const float* __restrict__ att_w2, const float* __restrict__ pos_emb,
                            const float* __restrict__ hidden, const int* __restrict__ mask,
                            const float* __restrict__ att_w1)
{
    __shared__ float sm_buf[DD];
    int t = threadIdx.x;
    if (blockIdx.x < PR_PW) {
        int i = blockIdx.x*256 + t;
        float v; __nv_bfloat16 hi, lo;
        if (i < 32768) {
            int n = i >> 8, k = i & 255;
            v = w1[k*128 + n];
            hi = __float2bfloat16(v); lo = __float2bfloat16(v - __bfloat162float(hi));
            g_w1b_hi[i] = hi; g_w1b_lo[i] = lo;
        } else if (i < 32768 + 65536) {
            int j = i - 32768;
            int n = j >> 7, k = j & 127;
            v = glu1_w[k*512 + n];
            hi = __float2bfloat16(v); lo = __float2bfloat16(v - __bfloat162float(hi));
            g_glub_hi[j] = hi; g_glub_lo[j] = lo;
        } else if (i < 114688) {
            int j = i - 98304;
            int n = j >> 7, k = j & 127;
            v = att_w2[k*128 + n];
            hi = __float2bfloat16(v); lo = __float2bfloat16(v - __bfloat162float(hi));
            g_aw2b_hi[j] = hi; g_aw2b_lo[j] = lo;
        }
    } else if (blockIdx.x < PR_HS) {
        int l = blockIdx.x - PR_PW;
        if (t < 128) sm_buf[t] = pos_emb[l*DD + t];
        __syncthreads();
        if (t < 128) {
            float a = 0.f;
            #pragma unroll 8
            for (int k = 0; k < 128; k++) a += sm_buf[k] * w1[k*128 + t];
            g_posw1[l*DD + t] = a;
        }
    } else {
        int b = blockIdx.x - PR_HS;
        if (t < 128) {
            float acc = 0.f, sm = 0.f;
            for (int l = 0; l < LL; l++) {
                float mk = (float)mask[b*LL + l];
                sm  += mk;
                acc += hidden[(size_t)(b*LL + l)*DD + t] * mk;
            }
            sm_buf[t] = acc / sm;
            if (t == 0) g_lens[b] = sm - (float)LEN_OPT;
        }
        __syncthreads();
        if (t < 128) {
            float a2 = 0.f;
            #pragma unroll 8
            for (int e = 0; e < DD; e++) a2 += sm_buf[e] * att_w1[e*DD + t];
            g_hsw1[b*DD + t] = a2;
        }
    }
}

// ---------------- fused front kernel (unchanged from R9) ---------------------------
#define FF_TMEM  0
#define FF_MBAR  8
#define FF_BIAS  64
#define FF_W2    2176
#define FF_ATTV  4288
#define FF_ALPHA 6400
#define FF_POSW1 8448
#define FF_AHID  34816
#define FF_ANH   100352
#define FF_B0    165888
#define FF_B1    198656
#define FF_SMEM  231424
#define IDESC64 ((1u<<4)|(1u<<7)|(1u<<10)|(8u<<17)|(8u<<24))

#if HAS_TCGEN05
__device__ __forceinline__ void f_load_chunk(uint32_t dst, const __nv_bfloat16* hi,
                                             const __nv_bfloat16* lo, int row0,
                                             int KD, int col0, int tid)
{
    #pragma unroll 8
    for (int i = tid; i < 2048; i += 256) {
        int half = i >> 10, rem = i & 1023;
        int r = rem >> 4, c8 = rem & 15;
        const __nv_bfloat16* src = (half ? lo : hi)
            + (size_t)(row0 + r)*KD + col0 + (c8 >> 3)*64 + (c8 & 7)*8;
        uint32_t byte = (uint32_t)((c8 >> 3)*8 + (r >> 3))*1024u
                      + (uint32_t)(r & 7)*128u + (uint32_t)(c8 & 7)*16u;
        cp16(dst + half*16384u + SWZ128(byte), src);
    }
    cp_commit();
}
__device__ __forceinline__ void f_mma_chunk(uint32_t d, uint32_t sbase,
                                            uint32_t aoff, uint32_t boff)
{
    uint64_t dAh = MAKE_DESC(sbase + aoff), dAl = MAKE_DESC(sbase + aoff + 32768);
    uint64_t dBh = MAKE_DESC(sbase + boff), dBl = MAKE_DESC(sbase + boff + 16384);
    uint64_t ad[3] = { dAh, dAh, dAl };
    uint64_t bd[3] = { dBh, dBl, dBh };
    #pragma unroll
    for (int p = 0; p < 3; p++)
        #pragma unroll
        for (int s = 0; s < 8; s++)
            mma_f16_ss(d, ad[p] + (uint64_t)((s >> 2)*1024 + (s & 3)*2),
                       bd[p] + (uint64_t)((s >> 2)*512 + (s & 3)*2),
                       IDESC64, !(p == 0 && s == 0));
}
#endif

__global__ void __launch_bounds__(256, 1) k_front(
    const float* __restrict__ hidden, const float* __restrict__ glu1_b,
    const float* __restrict__ w2, const float* __restrict__ att_v,
    const int* __restrict__ mask, const float* __restrict__ pos_emb,
    const float* __restrict__ w1)
{
#if HAS_TCGEN05
    extern __shared__ char smem[];
    uint32_t sbase = smem_u32(smem);
    int tid = threadIdx.x, wid = tid >> 5, lane = tid & 31;
    int mtile = blockIdx.x;
    uint32_t mbar = sbase + FF_MBAR;

    if (tid == 0)
        asm volatile("mbarrier.init.shared.b64 [%0], 1;" :: "r"(mbar) : "memory");
    if (wid == 0)
        asm volatile("tcgen05.alloc.cta_group::1.sync.aligned.shared::cta.b32 [%0], %1;"
                     :: "r"(sbase + FF_TMEM), "r"(512u) : "memory");
    __syncthreads();
    uint32_t tmem;
    asm volatile("ld.shared.b32 %0, [%1];" : "=r"(tmem) : "r"(sbase + FF_TMEM));

    f_load_chunk(sbase + FF_B0, g_w1b_hi, g_w1b_lo,  0, 256, 128, tid);
    f_load_chunk(sbase + FF_B1, g_w1b_hi, g_w1b_lo, 64, 256, 128, tid);

    for (int i = tid; i < 128*16; i += 256) {
        int r = i >> 4, c8 = i & 15;
        int m = mtile*128 + r;
        int col = (c8 >> 3)*64 + (c8 & 7)*8;
        const float* src = hidden + (size_t)m*DD + col;
        float f[8];
        *(float4*)f       = *(const float4*)src;
        *(float4*)(f + 4) = *(const float4*)(src + 4);
        __align__(16) ushort h[8], l[8];
        #pragma unroll
        for (int q = 0; q < 8; q++) { float rem; h[q] = bf_hi_us(f[q], rem); l[q] = bf_us(rem); }
        uint32_t byte = (uint32_t)((c8 >> 3)*16 + (r >> 3))*1024u
                      + (uint32_t)(r & 7)*128u + (uint32_t)(c8 & 7)*16u;
        uint32_t sw = SWZ128(byte);
        *(uint4*)(smem + FF_AHID + sw)         = *(uint4*)h;
        *(uint4*)(smem + FF_AHID + 32768 + sw) = *(uint4*)l;
    }
    {
        float* bias = (float*)(smem + FF_BIAS);
        float* w2s  = (float*)(smem + FF_W2);
        float* avs  = (float*)(smem + FF_ATTV);
        for (int i = tid; i < 512; i += 256) { bias[i] = glu1_b[i]; w2s[i] = w2[i]; avs[i] = att_v[i]; }
        float* pw = (float*)(smem + FF_POSW1);
        for (int i = tid; i < 50*128; i += 256) pw[(i >> 7)*129 + (i & 127)] = g_posw1[i];
    }
    cp_wait0();
    __syncthreads();

    if (wid == 0 && elect1()) {
        asm volatile("fence.proxy.async.shared::cta;" ::: "memory");
        f_mma_chunk(tmem +  0, sbase, FF_AHID, FF_B0);
        f_mma_chunk(tmem + 64, sbase, FF_AHID, FF_B1);
        TCOMMIT(mbar);
    }
    MBAR_WAIT(mbar, 0u);

    f_load_chunk(sbase + FF_B0, g_aw2b_hi, g_aw2b_lo,  0, 128, 0, tid);
    f_load_chunk(sbase + FF_B1, g_aw2b_hi, g_aw2b_lo, 64, 128, 0, tid);
    cp_wait0();
    __syncthreads();
    if (wid == 0 && elect1()) {
        asm volatile("fence.proxy.async.shared::cta;" ::: "memory");
        f_mma_chunk(tmem + 128, sbase, FF_AHID, FF_B0);
        f_mma_chunk(tmem + 192, sbase, FF_AHID, FF_B1);
        TCOMMIT(mbar);
    }
    MBAR_WAIT(mbar, 1u);
    asm volatile("tcgen05.fence::after_thread_sync;" ::: "memory");

    f_load_chunk(sbase + FF_B0, g_glub_hi, g_glub_lo,  0, 128, 0, tid);
    f_load_chunk(sbase + FF_B1, g_glub_hi, g_glub_lo, 64, 128, 0, tid);

    {
        int sub = wid & 3;
        int mloc = sub*32 + lane;
        int mglob = mtile*128 + mloc;
        if (wid < 4) {
            const float* prow = (const float*)(smem + FF_POSW1) + (mglob % LL)*129;
            #pragma unroll 1
            for (int ch = 0; ch < 4; ch++) {
                uint32_t r[32];
                LDTM32(r, tmem + ch*32);
                asm volatile("tcgen05.wait::ld.sync.aligned;" ::: "memory");
                #pragma unroll
                for (int q = 0; q < 4; q++) {
                    __align__(16) ushort h8[8], l8[8];
                    #pragma unroll
                    for (int u = 0; u < 8; u++) {
                        int c = ch*32 + q*8 + u;
                        float v = tanhf(__uint_as_float(r[q*8 + u]) + prow[c]);
                        float rem; h8[u] = bf_hi_us(v, rem); l8[u] = bf_us(rem);
                    }
                    int c8 = ch*4 + q;
                    uint32_t byte = (uint32_t)((c8 >> 3)*16 + (mloc >> 3))*1024u
                                  + (uint32_t)(mloc & 7)*128u + (uint32_t)(c8 & 7)*16u;
                    uint32_t sw = SWZ128(byte);
                    *(uint4*)(smem + FF_ANH + sw)         = *(uint4*)h8;
                    *(uint4*)(smem + FF_ANH + 32768 + sw) = *(uint4*)l8;
                }
            }
        } else {
            const float* hsrow = g_hsw1 + (mglob / LL)*DD;
            const float* avs = (const float*)(smem + FF_ATTV);
            float acc[4] = {};
            #pragma unroll 1
            for (int ch = 0; ch < 4; ch++) {
                uint32_t r[32];
                LDTM32(r, tmem + 128 + ch*32);
                asm volatile("tcgen05.wait::ld.sync.aligned;" ::: "memory");
                #pragma unroll
                for (int j = 0; j < 32; j++) {
                    int c = ch*32 + j;
                    float t = tanhf(__uint_as_float(r[j]) + hsrow[c]);
                    #pragma unroll
                    for (int k = 0; k < 4; k++) acc[k] += t * avs[c*4 + k];
                }
            }
            float* al = (float*)(smem + FF_ALPHA);
            #pragma unroll
            for (int k = 0; k < 4; k++) al[mloc*4 + k] = sigmoidf(acc[k]);
        }
        asm volatile("tcgen05.fence::before_thread_sync;" ::: "memory");
    }
    cp_wait0();
    __syncthreads();

    int ph = 0;
    for (int p = 0; p < 4; p++) {
        if (wid == 0 && elect1()) {
            asm volatile("tcgen05.fence::after_thread_sync;" ::: "memory");
            asm volatile("fence.proxy.async.shared::cta;" ::: "memory");
            f_mma_chunk(tmem + (2*p    )*64, sbase, FF_ANH, FF_B0);
            f_mma_chunk(tmem + (2*p + 1)*64, sbase, FF_ANH, FF_B1);
            TCOMMIT(mbar);
        }
        MBAR_WAIT(mbar, (uint32_t)(ph & 1));
        ph++;
        if (p < 3) {
            f_load_chunk(sbase + FF_B0, g_glub_hi, g_glub_lo, (2*p + 2)*64, 128, 0, tid);
            f_load_chunk(sbase + FF_B1, g_glub_hi, g_glub_lo, (2*p + 3)*64, 128, 0, tid);
            cp_wait0();
            __syncthreads();
        }
    }
    asm volatile("tcgen05.fence::after_thread_sync;" ::: "memory");

    {
        int sub = wid & 3, g = wid >> 2;
        int mloc = sub*32 + lane;
        int mglob = mtile*128 + mloc;
        const float* bias = (const float*)(smem + FF_BIAS);
        const float* w2s  = (const float*)(smem + FF_W2);
        float acc0 = 0.f, acc1 = 0.f;
        #pragma unroll 1
        for (int cc = 0; cc < 8; cc++) {
            int ch = g*8 + cc;
            uint32_t r[32];
            LDTM32(r, tmem + ch*32);
            asm volatile("tcgen05.wait::ld.sync.aligned;" ::: "memory");
            int k = ch >> 2;
            float a = 0.f;
            #pragma unroll
            for (int j = 0; j < 32; j++) {
                int n = ch*32 + j;
                float s = sigmoidf(__uint_as_float(r[j]) + bias[n]);
                a += s * w2s[(n & 127)*4 + k];
            }
            if (cc < 4) acc0 += a; else acc1 += a;
        }
        const float* al = (const float*)(smem + FF_ALPHA);
        float mk = (float)mask[mglob];
        float2 o;
        o.x = acc0 * (0.5f + al[mloc*4 + 2*g    ]) * mk;
        o.y = acc1 * (0.5f + al[mloc*4 + 2*g + 1]) * mk;
        *(float2*)(g_beta + mglob*4 + 2*g) = o;
    }
    __syncthreads();
    if (wid == 0)
        asm volatile("tcgen05.dealloc.cta_group::1.sync.aligned.b32 %0, %1;"
                     :: "r"(tmem), "r"(512u));
#else
    int tid = threadIdx.x;
    if (tid >= 128) return;
    int m = blockIdx.x*128 + tid;
    float nh[128];
    for (int n = 0; n < 128; n++) {
        float acc = 0.f;
        for (int k = 0; k < 128; k++) acc += pos_emb[(m % LL)*DD + k] * w1[k*128 + n];
        for (int k = 0; k < 128; k++) {
            float b = __bfloat162float(g_w1b_hi[n*256 + 128 + k]) + __bfloat162float(g_w1b_lo[n*256 + 128 + k]);
            acc += hidden[(size_t)m*DD + k] * b;
        }
        nh[n] = tanhf(acc);
    }
    float alpha[4] = {};
    for (int n = 0; n < 128; n++) {
        float x = 0.f;
        for (int k = 0; k < 128; k++)
            x += hidden[(size_t)m*DD + k] *
                 (__bfloat162float(g_aw2b_hi[n*128 + k]) + __bfloat162float(g_aw2b_lo[n*128 + k]));
        float t = tanhf(x + g_hsw1[(m / LL)*DD + n]);
        for (int k = 0; k < 4; k++) alpha[k] += t * att_v[n*4 + k];
    }
    for (int k = 0; k < 4; k++) alpha[k] = sigmoidf(alpha[k]);
    float acc[4] = {};
    for (int n = 0; n < 512; n++) {
        float x = 0.f;
        for (int k = 0; k < 128; k++)
            x += nh[k] * (__bfloat162float(g_glub_hi[n*128 + k]) + __bfloat162float(g_glub_lo[n*128 + k]));
        float s = sigmoidf(x + glu1_b[n]);
        acc[n >> 7] += s * w2[(n & 127)*4 + (n >> 7)];
    }
    float mk = (float)mask[m];
    for (int k = 0; k < 4; k++)
        g_beta[m*4 + k] = acc[k] * (0.5f + alpha[k]) * mk;
#endif
}

// ---------------- select (blocks 0..255) + loss (block 256) ------------------------
__global__ void k_sel_loss(const float* __restrict__ hidden, float* __restrict__ out_scalar)
{
    if (blockIdx.x < BB) {
        if (threadIdx.x >= 128) return;
        int b = blockIdx.x, t = threadIdx.x;
        float acc[4] = {};
        for (int l = 0; l < LL; l++) {
            float h = hidden[(size_t)(b*LL + l)*DD + t];
            float4 be = *(const float4*)(&g_beta[(b*LL + l)*4]);
            acc[0] += be.x*h; acc[1] += be.y*h; acc[2] += be.z*h; acc[3] += be.w*h;
        }
        #pragma unroll
        for (int k = 0; k < 4; k++) {
            float v = acc[k];
            __nv_bfloat16 hi = __float2bfloat16(v);
            __nv_bfloat16 lo = __float2bfloat16(v - __bfloat162float(hi));
            g_sel_hi[(b*4 + k)*DD + t] = hi;
            g_sel_lo[(b*4 + k)*DD + t] = lo;
        }
    } else {
        int b = threadIdx.x;
        float n2[4] = {};
        for (int l = 0; l < LL; l++) {
            float4 be = *(const float4*)(&g_beta[(b*LL + l)*4]);
            n2[0]+=be.x*be.x; n2[1]+=be.y*be.y; n2[2]+=be.z*be.z; n2[3]+=be.w*be.w;
        }
        float inv[4];
        #pragma unroll
        for (int k = 0; k < 4; k++) inv[k] = 1.0f / fmaxf(sqrtf(n2[k]), EPS_N);
        float G[6] = {};
        for (int l = 0; l < LL; l++) {
            float4 be = *(const float4*)(&g_beta[(b*LL + l)*4]);
            float v0=be.x*inv[0], v1=be.y*inv[1], v2=be.z*inv[2], v3=be.w*inv[3];
            G[0]+=v0*v1; G[1]+=v0*v2; G[2]+=v0*v3;
            G[3]+=v1*v2; G[4]+=v1*v3; G[5]+=v2*v3;
        }
        float sim = 0.f;
        #pragma unroll
        for (int i = 0; i < 6; i++) sim += fabsf(G[i]);
        sim *= (2.0f / (KK*(KK-1)));
        float lossb = sigmoidf(sim * g_lens[b]);
        __shared__ float red[BB];
        red[b] = lossb;  __syncthreads();
        for (int s = BB/2; s > 0; s >>= 1) {
            if (b < s) red[b] += red[b + s];
            __syncthreads();
        }
        if (b == 0) *out_scalar = red[0] * BETA_S;
    }
}

// ---------------- scores: persistent CTAs, N=192 tiles, TS-mode MMA ----------------
// TMEM: D0 @0 (192), D1 @192 (192), A_hi @384 (64), A_lo @448 (64).
#define SC_NT 192
#define SC_TILES 261              // ceil(49999/192)
#define SC_STRIDE 18
#define S_IDESC ((1u<<4) | (1u<<7) | (1u<<10) | (24u<<17) | (8u<<24))
#define S2_TMEM  0
#define S2_MBAR0 8
#define S2_MBAR1 16
#define S2_B0    1024
#define S2_BHALF 49152            // hi/lo halves within a buffer
#define S2_B1    (1024 + 98304)   // 99328
#define S2_STG   (1024 + 196608)  // 197632
#define S2_SMEM_TOT (197632 + 8*32*33*4)  // 231424

#if HAS_TCGEN05
__device__ __forceinline__ void s2_load_b(uint32_t bufbase, int vtile, int tid)
{
    int vbase = vtile * SC_NT;
    #pragma unroll 6
    for (int i = tid; i < 6144; i += 256) {
        int half = (i >= 3072);
        int rem = i - (half << 11) - (half << 10);       // i - half*3072
        int r = rem >> 4, c8 = rem & 15;
        int v = vbase + r; if (v > VM1 - 1) v = VM1 - 1;
        const __nv_bfloat16* src = (half ? g_emb_lo : g_emb_hi)
                                 + (size_t)v*DD + (c8 >> 3)*64 + (c8 & 7)*8;
        uint32_t byte = (uint32_t)((c8 >> 3)*24 + (r >> 3))*1024u
                      + (uint32_t)(r & 7)*128u + (uint32_t)(c8 & 7)*16u;
        cp16(bufbase + (uint32_t)half*S2_BHALF + SWZ128(byte), src);
    }
    cp_commit();
}
__device__ __forceinline__ void s2_mma(uint32_t tmem, int dhalf, uint32_t sbase,
                                       uint32_t bufoff, uint32_t mbar)
{
    asm volatile("fence.proxy.async.shared::cta;" ::: "memory");
    uint64_t dBh = MAKE_DESC(sbase + bufoff);
    uint64_t dBl = MAKE_DESC(sbase + bufoff + S2_BHALF);
    uint32_t d  = tmem + dhalf*SC_NT;
    uint32_t aH = tmem + 384, aL = tmem + 448;
    uint32_t ap[3] = { aH, aH, aL };
    uint64_t bp[3] = { dBh, dBl, dBh };
    #pragma unroll
    for (int p = 0; p < 3; p++) {
        #pragma unroll
        for (int s = 0; s < 8; s++) {
            mma_f16_ts(d, ap[p] + s*8,
                       bp[p] + (uint64_t)((s >> 2)*1536 + (s & 3)*2),
                       S_IDESC, !(p == 0 && s == 0));
        }
    }
    asm volatile(
        "tcgen05.commit.cta_group::1.mbarrier::arrive::one.shared::cluster.b64 [%0];"
        :: "r"(mbar) : "memory");
}
#endif

__global__ void __launch_bounds__(256, 1) k_scores_mma(
        float* __restrict__ maxsc, float* __restrict__ scores)
{
#if HAS_TCGEN05
    extern __shared__ char smem[];
    uint32_t sbase = smem_u32(smem);
    int tid = threadIdx.x, wid = tid >> 5, lane = tid & 31;
    int mtile = blockIdx.x;
    int y = blockIdx.y;
    int nt = (SC_TILES - y + SC_STRIDE - 1) / SC_STRIDE;

    if (tid == 0) {
        asm volatile("mbarrier.init.shared.b64 [%0], 1;" :: "r"(sbase + S2_MBAR0) : "memory");
        asm volatile("mbarrier.init.shared.b64 [%0], 1;" :: "r"(sbase + S2_MBAR1) : "memory");
    }
    if (wid == 0)
        asm volatile("tcgen05.alloc.cta_group::1.sync.aligned.shared::cta.b32 [%0], %1;"
                     :: "r"(sbase + S2_TMEM), "r"(512u) : "memory");
    __syncthreads();
    uint32_t tmem;
    asm volatile("ld.shared.b32 %0, [%1];" : "=r"(tmem) : "r"(sbase + S2_TMEM));

    s2_load_b(sbase + S2_B0, y, tid);
    s2_load_b(sbase + S2_B1, y + SC_STRIDE, tid);
    if (tid < 128) {
        int m = mtile*128 + tid;
        const uint32_t* ph = (const uint32_t*)g_sel_hi + (size_t)m*64;
        const uint32_t* pl = (const uint32_t*)g_sel_lo + (size_t)m*64;
        uint32_t woff = (uint32_t)(tid >> 5) << 21;
        uint32_t a[32];
        #pragma unroll
        for (int q = 0; q < 32; q++) a[q] = ph[q];
        STTM32(tmem + 384 + woff, a);
        #pragma unroll
        for (int q = 0; q < 32; q++) a[q] = ph[32 + q];
        STTM32(tmem + 416 + woff, a);
        #pragma unroll
        for (int q = 0; q < 32; q++) a[q] = pl[q];
        STTM32(tmem + 448 + woff, a);
        #pragma unroll
        for (int q = 0; q < 32; q++) a[q] = pl[32 + q];
        STTM32(tmem + 480 + woff, a);
        asm volatile("tcgen05.wait::st.sync.aligned;" ::: "memory");
    }
    cp_wait1();
    __syncthreads();
    if (wid == 0 && elect1())
        s2_mma(tmem, 0, sbase, S2_B0, sbase + S2_MBAR0);

    int sub = wid & 3, h = wid >> 2;
    float* stg = (float*)(smem + S2_STG + wid*(32*33*4));
    // hoisted store bases
    size_t base_b0 = (size_t)(mtile*32 + sub*8) * VM1;
    const size_t KSTR = (size_t)BB * VM1;

    for (int i = 0; i < nt; i++) {
        cp_wait0();
        MBAR_WAIT(sbase + ((i & 1) ? S2_MBAR1 : S2_MBAR0), (uint32_t)((i >> 1) & 1));
        asm volatile("tcgen05.fence::after_thread_sync;" ::: "memory");
        __syncthreads();

        if (i + 1 < nt && wid == 0 && elect1())
            s2_mma(tmem, (i + 1) & 1, sbase,
                   ((i + 1) & 1) ? S2_B1 : S2_B0,
                   sbase + (((i + 1) & 1) ? S2_MBAR1 : S2_MBAR0));
        if (i + 2 < nt)
            s2_load_b(sbase + ((i & 1) ? S2_B1 : S2_B0), y + (i + 2)*SC_STRIDE, tid);

        uint32_t dbase = tmem + (i & 1)*SC_NT;
        int vb = (y + i*SC_STRIDE)*SC_NT;
        #pragma unroll 1
        for (int cc = 0; cc < 3; cc++) {
            int col0 = h*96 + cc*32;
            uint32_t r[32];
            LDTM32(r, dbase + col0);
            asm volatile("tcgen05.wait::ld.sync.aligned;" ::: "memory");
            #pragma unroll
            for (int c = 0; c < 32; c++) stg[lane*33 + c] = __uint_as_float(r[c]);
            __syncwarp();
            int v = vb + col0 + lane;
            bool ok = v < VM1;
            float* sc0 = scores + base_b0 + v;
            float* mx0 = maxsc + base_b0 + v;
            #pragma unroll
            for (int lb = 0; lb < 8; lb++) {
                float mx = -3.402823466e38f;
                #pragma unroll
                for (int j = 0; j < 4; j++) {
                    float x = stg[(lb*4 + j)*33 + lane];
                    if (ok) __stcs(sc0 + (size_t)lb*VM1 + (size_t)j*KSTR, x);
                    mx = fmaxf(mx, x);
                }
                if (ok) __stcs(mx0 + (size_t)lb*VM1, mx);
            }
            __syncwarp();
        }
    }
    __syncthreads();
    if (wid == 0)
        asm volatile("tcgen05.dealloc.cta_group::1.sync.aligned.b32 %0, %1;"
                     :: "r"(tmem), "r"(512u));
#else
    int tid = threadIdx.x;
    int mtile = blockIdx.x;
    int y = blockIdx.y;
    for (int vt = y; vt < SC_TILES; vt += SC_STRIDE) {
        int vbase = vt*SC_NT;
        for (int p = tid; p < 32*SC_NT; p += 256) {
            int bl = p / SC_NT, vv = vbase + (p % SC_NT);
            if (vv >= VM1) continue;
            int b = mtile*32 + bl;
            float mx = -3.402823466e38f;
            for (int k = 0; k < 4; k++) {
                int m = (b*4 + k);
                float acc = 0.f;
                for (int d = 0; d < DD; d++) {
                    float a = __bfloat162float(g_sel_hi[m*DD + d]) + __bfloat162float(g_sel_lo[m*DD + d]);
                    float e = __bfloat162float(g_emb_hi[(size_t)vv*DD + d]) + __bfloat162float(g_emb_lo[(size_t)vv*DD + d]);
                    acc += a * e;
                }
                scores[((size_t)k*BB + b)*VM1 + vv] = acc;
                mx = fmaxf(mx, acc);
            }
            maxsc[(size_t)b*VM1 + vv] = mx;
        }
    }
#endif
}

// ---------------- launch: forked capture graph -------------------------------------
extern "C" void kernel_launch(void* const* d_in, const int* in_sizes, int n_in,
                              void* d_out, int out_size)
{
    const float* hidden  = (const float*)d_in[0];
    const int*   mask    = (const int*)  d_in[1];
    const float* pos_emb = (const float*)d_in[2];
    const float* w1      = (const float*)d_in[3];
    const float* w2      = (const float*)d_in[4];
    const float* glu1_w  = (const float*)d_in[5];
    const float* glu1_b  = (const float*)d_in[6];
    const float* att_w1  = (const float*)d_in[7];
    const float* att_w2  = (const float*)d_in[8];
    const float* att_v   = (const float*)d_in[9];
    const float* emb     = (const float*)d_in[10];

    float* out    = (float*)d_out;
    float* maxsc  = out;                                   // [B, Vm1]
    float* scalar = out + (size_t)BB*VM1;                  // [1]
    float* scores = out + (size_t)BB*VM1 + 1;              // [K, B, Vm1]

    static cudaStream_t s2 = nullptr;
    static cudaEvent_t ev_fork = nullptr, ev_emb = nullptr;
    if (!s2) {
        cudaStreamCreateWithFlags(&s2, cudaStreamNonBlocking);
        cudaEventCreateWithFlags(&ev_fork, cudaEventDisableTiming);
        cudaEventCreateWithFlags(&ev_emb, cudaEventDisableTiming);
        cudaFuncSetAttribute(k_scores_mma,
                             cudaFuncAttributeMaxDynamicSharedMemorySize, S2_SMEM_TOT);
        cudaFuncSetAttribute(k_front,
                             cudaFuncAttributeMaxDynamicSharedMemorySize, FF_SMEM);
    }

    // fork: emb prep runs parallel to the front chain
    cudaEventRecord(ev_fork, 0);
    cudaStreamWaitEvent(s2, ev_fork, 0);
    k_prep_emb<<<(VM1 + 7)/8, 256, 0, s2>>>(emb);
    cudaEventRecord(ev_emb, s2);

    k_prep_rest<<<PR_GRID, 256>>>(w1, glu1_w, att_w2, pos_emb, hidden, mask, att_w1);
    k_front<<<100, 256, FF_SMEM>>>(hidden, glu1_b, w2, att_v, mask, pos_emb, w1);
    k_sel_loss<<<BB + 1, 256>>>(hidden, scalar);

    // join: scores needs both sel (main stream) and emb (side stream)
    cudaStreamWaitEvent(0, ev_emb, 0);
    k_scores_mma<<<dim3(8, SC_STRIDE), 256, S2_SMEM_TOT>>>(maxsc, scores);
}

// round 11
// speedup vs baseline: 1.1305x; 1.1305x over previous
#include <cuda_runtime.h>
#include <cuda_bf16.h>
#include <cstdint>

// Problem constants
#define BB   256
#define LL   50
#define DD   128
#define KK   4
#define VV   50000
#define VM1  49999
#define BL   (BB*LL)        // 12800
#define LEN_OPT 5
#define BETA_S 0.01f
#define EPS_N  1e-12f

// Arch-specific (sm_103a) feature gate
#if defined(__CUDA_ARCH__)
#  if defined(__CUDA_ARCH_FEAT_SM103_ALL) || defined(__CUDA_ARCH_FEAT_SM100_ALL) || \
      defined(__CUDA_ARCH_FEAT_SM101_ALL) || \
      (defined(__CUDA_ARCH_SPECIFIC__) && (__CUDA_ARCH_SPECIFIC__ >= 1000)) || \
      (defined(__CUDA_ARCH_FAMILY_SPECIFIC__) && (__CUDA_ARCH_FAMILY_SPECIFIC__ >= 1000))
#    define HAS_TCGEN05 1
#  else
#    define HAS_TCGEN05 0
#  endif
#else
#  define HAS_TCGEN05 0
#endif

// ---------------- scratch (static device globals; no allocation) ----------------
__device__ float g_hsw1 [BB*DD];
__device__ float g_lens [BB];
__device__ float g_posw1[50*DD];
__device__ float g_beta [BL*KK];
__device__ __align__(16) __nv_bfloat16 g_sel_hi[BB*KK*DD];
__device__ __align__(16) __nv_bfloat16 g_sel_lo[BB*KK*DD];
__device__ __align__(16) __nv_bfloat16 g_emb_hi[(size_t)VM1*DD];
__device__ __align__(16) __nv_bfloat16 g_emb_lo[(size_t)VM1*DD];
__device__ __align__(16) __nv_bfloat16 g_w1b_hi[128*256],  g_w1b_lo[128*256];
__device__ __align__(16) __nv_bfloat16 g_glub_hi[512*128], g_glub_lo[512*128];
__device__ __align__(16) __nv_bfloat16 g_aw2b_hi[128*128], g_aw2b_lo[128*128];

__device__ __forceinline__ float sigmoidf(float x){ return 1.0f/(1.0f+expf(-x)); }

__device__ __forceinline__ uint32_t smem_u32(const void* p) {
    uint32_t a;
    asm("{ .reg .u64 t; cvta.to.shared.u64 t, %1; cvt.u32.u64 %0, t; }" : "=r"(a) : "l"(p));
    return a;
}
#define SWZ128(x) ((x) ^ (((x) >> 3) & 0x70))

static constexpr uint64_t SMEM_DESC_BASE_SW128 =
    (uint64_t(2) << 61) | (uint64_t(1) << 46) | (uint64_t(64) << 32) | (uint64_t(1) << 16);
#define MAKE_DESC(addr) (SMEM_DESC_BASE_SW128 | ((uint64_t)((addr) >> 4) & 0x3FFF))

#if HAS_TCGEN05
__device__ __forceinline__ uint32_t elect1() {
    uint32_t p;
    asm volatile("{ .reg .pred p; elect.sync _|p, 0xFFFFFFFF; selp.b32 %0,1,0,p; }" : "=r"(p));
    return p;
}
__device__ __forceinline__ void mma_f16_ss(uint32_t d_tmem, uint64_t a_desc,
                                           uint64_t b_desc, uint32_t idesc, int en)
{
    asm volatile(
        "{\n\t.reg .pred p;\n\t"
        "setp.ne.u32 p, %4, 0;\n\t"
        "tcgen05.mma.cta_group::1.kind::f16 [%0], %1, %2, %3, {%5,%5,%5,%5}, p;\n\t}"
        :: "r"(d_tmem), "l"(a_desc), "l"(b_desc), "r"(idesc), "r"(en), "r"(0u)
        : "memory");
}
__device__ __forceinline__ void mma_f16_ts(uint32_t d_tmem, uint32_t a_tmem,
                                           uint64_t b_desc, uint32_t idesc, int en)
{
    asm volatile(
        "{\n\t.reg .pred p;\n\t"
        "setp.ne.u32 p, %4, 0;\n\t"
        "tcgen05.mma.cta_group::1.kind::f16 [%0], [%1], %2, %3, {%5,%5,%5,%5}, p;\n\t}"
        :: "r"(d_tmem), "r"(a_tmem), "l"(b_desc), "r"(idesc), "r"(en), "r"(0u)
        : "memory");
}
__device__ __forceinline__ void cp16(uint32_t dst, const void* src) {
    asm volatile("cp.async.cg.shared.global [%0], [%1], 16;" :: "r"(dst), "l"(src));
}
__device__ __forceinline__ void cp_commit() { asm volatile("cp.async.commit_group;" ::: "memory"); }
__device__ __forceinline__ void cp_wait0()  { asm volatile("cp.async.wait_group 0;" ::: "memory"); }
__device__ __forceinline__ void cp_wait1()  { asm volatile("cp.async.wait_group 1;" ::: "memory"); }
#define MBAR_WAIT(mbar, par) do {                                              \
    asm volatile(                                                              \
        "{\n\t.reg .pred P1;\n\t"                                              \
        "WL_%=:\n\t"                                                           \
        "mbarrier.try_wait.parity.acquire.cta.shared::cta.b64 P1, [%0], %1, 0x989680;\n\t" \
        "@P1 bra.uni WD_%=;\n\t"                                               \
        "bra.uni WL_%=;\n\t"                                                   \
        "WD_%=:\n\t}" :: "r"(mbar), "r"(par) : "memory");                      \
} while(0)
#define TCOMMIT(mbar)                                                          \
    asm volatile(                                                              \
        "tcgen05.commit.cta_group::1.mbarrier::arrive::one.shared::cluster.b64 [%0];" \
        :: "r"(mbar) : "memory")
#define LDTM32(r, addr)                                                        \
    asm volatile(                                                              \
        "tcgen05.ld.sync.aligned.32x32b.x32.b32 "                              \
        "{%0,%1,%2,%3,%4,%5,%6,%7,%8,%9,%10,%11,%12,%13,%14,%15,"              \
        "%16,%17,%18,%19,%20,%21,%22,%23,%24,%25,%26,%27,%28,%29,%30,%31}, [%32];" \
        : "=r"(r[0]),"=r"(r[1]),"=r"(r[2]),"=r"(r[3]),"=r"(r[4]),"=r"(r[5]),"=r"(r[6]),"=r"(r[7]), \
          "=r"(r[8]),"=r"(r[9]),"=r"(r[10]),"=r"(r[11]),"=r"(r[12]),"=r"(r[13]),"=r"(r[14]),"=r"(r[15]), \
          "=r"(r[16]),"=r"(r[17]),"=r"(r[18]),"=r"(r[19]),"=r"(r[20]),"=r"(r[21]),"=r"(r[22]),"=r"(r[23]), \
          "=r"(r[24]),"=r"(r[25]),"=r"(r[26]),"=r"(r[27]),"=r"(r[28]),"=r"(r[29]),"=r"(r[30]),"=r"(r[31]) \
        : "r"(addr))
#define STTM32(addr, r)                                                        \
    asm volatile(                                                              \
        "tcgen05.st.sync.aligned.32x32b.x32.b32 [%0], "                        \
        "{%1,%2,%3,%4,%5,%6,%7,%8,%9,%10,%11,%12,%13,%14,%15,%16,"             \
        "%17,%18,%19,%20,%21,%22,%23,%24,%25,%26,%27,%28,%29,%30,%31,%32};"    \
        :: "r"(addr),                                                          \
           "r"(r[0]),"r"(r[1]),"r"(r[2]),"r"(r[3]),"r"(r[4]),"r"(r[5]),"r"(r[6]),"r"(r[7]), \
           "r"(r[8]),"r"(r[9]),"r"(r[10]),"r"(r[11]),"r"(r[12]),"r"(r[13]),"r"(r[14]),"r"(r[15]), \
           "r"(r[16]),"r"(r[17]),"r"(r[18]),"r"(r[19]),"r"(r[20]),"r"(r[21]),"r"(r[22]),"r"(r[23]), \
           "r"(r[24]),"r"(r[25]),"r"(r[26]),"r"(r[27]),"r"(r[28]),"r"(r[29]),"r"(r[30]),"r"(r[31]) \
        : "memory")
#endif

__device__ __forceinline__ ushort bf_hi_us(float v, float& rem) {
    __nv_bfloat16 hb = __float2bfloat16(v);
    rem = v - __bfloat162float(hb);
    return *reinterpret_cast<ushort*>(&hb);
}
__device__ __forceinline__ ushort bf_us(float v) {
    __nv_bfloat16 b = __float2bfloat16(v);
    return *reinterpret_cast<ushort*>(&b);
}

// ---------------- merged prep ------------------------------------------------------
// blocks [0,6250): emb normalize + hi/lo split
// blocks [6250,6698): weight transpose + split
// blocks [6698,6748): posw1
// blocks [6748,7004): hs/lens/hsw1 (2-way L split)
#define NPE_BLOCKS 6250
#define W_BASE  NPE_BLOCKS
#define PW_BASE (NPE_BLOCKS + 448)
#define HS_BASE (PW_BASE + 50)
#define PREP_GRID (HS_BASE + 256)
__global__ void k_prep(const float* __restrict__ emb, const float* __restrict__ w1,
                       const float* __restrict__ glu1_w, const float* __restrict__ att_w2,
                       const float* __restrict__ pos_emb, const float* __restrict__ hidden,
                       const int* __restrict__ mask, const float* __restrict__ att_w1)
{
    __shared__ float sm_buf[DD];
    __shared__ float part[2][DD];
    __shared__ float psum[2];
    int t = threadIdx.x;
    if (blockIdx.x < NPE_BLOCKS) {
        int w = t >> 5, lane = t & 31;
        int v = blockIdx.x*8 + w;
        if (v >= VM1) return;
        float4 x = *(const float4*)(emb + (size_t)(1 + v)*DD + lane*4);
        float s = x.x*x.x + x.y*x.y + x.z*x.z + x.w*x.w;
        #pragma unroll
        for (int o = 16; o > 0; o >>= 1) s += __shfl_xor_sync(0xffffffffu, s, o);
        float inv = 1.0f / fmaxf(sqrtf(s), EPS_N);
        float n[4] = {x.x*inv, x.y*inv, x.z*inv, x.w*inv};
        __nv_bfloat16 hi[4], lo[4];
        #pragma unroll
        for (int i = 0; i < 4; i++) {
            hi[i] = __float2bfloat16(n[i]);
            lo[i] = __float2bfloat16(n[i] - __bfloat162float(hi[i]));
        }
        *(uint64_t*)(&g_emb_hi[(size_t)v*DD + lane*4]) = *(uint64_t*)hi;
        *(uint64_t*)(&g_emb_lo[(size_t)v*DD + lane*4]) = *(uint64_t*)lo;
    } else if (blockIdx.x < PW_BASE) {
        int i = (blockIdx.x - W_BASE)*256 + t;
        float v; __nv_bfloat16 hi, lo;
        if (i < 32768) {
            int n = i >> 8, k = i & 255;
            v = w1[k*128 + n];
            hi = __float2bfloat16(v); lo = __float2bfloat16(v - __bfloat162float(hi));
            g_w1b_hi[i] = hi; g_w1b_lo[i] = lo;
        } else if (i < 32768 + 65536) {
            int j = i - 32768;
            int n = j >> 7, k = j & 127;
            v = glu1_w[k*512 + n];
            hi = __float2bfloat16(v); lo = __float2bfloat16(v - __bfloat162float(hi));
            g_glub_hi[j] = hi; g_glub_lo[j] = lo;
        } else if (i < 114688) {
            int j = i - 98304;
            int n = j >> 7, k = j & 127;
            v = att_w2[k*128 + n];
            hi = __float2bfloat16(v); lo = __float2bfloat16(v - __bfloat162float(hi));
            g_aw2b_hi[j] = hi; g_aw2b_lo[j] = lo;
        }
    } else if (blockIdx.x < HS_BASE) {
        int l = blockIdx.x - PW_BASE;
        if (t < 128) sm_buf[t] = pos_emb[l*DD + t];
        __syncthreads();
        if (t < 128) {
            float a = 0.f;
            #pragma unroll 8
            for (int k = 0; k < 128; k++) a += sm_buf[k] * w1[k*128 + t];
            g_posw1[l*DD + t] = a;
        }
    } else {
        int b = blockIdx.x - HS_BASE;
        int d = t & 127, lh = t >> 7;
        float acc = 0.f, sm = 0.f;
        #pragma unroll 5
        for (int l = lh*25; l < lh*25 + 25; l++) {
            float mk = (float)mask[b*LL + l];
            sm  += mk;
            acc += hidden[(size_t)(b*LL + l)*DD + d] * mk;
        }
        part[lh][d] = acc;
        if (d == 0) psum[lh] = sm;
        __syncthreads();
        if (t < 128) {
            float stot = psum[0] + psum[1];
            sm_buf[t] = (part[0][t] + part[1][t]) / stot;
            if (t == 0) g_lens[b] = stot - (float)LEN_OPT;
        }
        __syncthreads();
        if (t < 128) {
            float a2 = 0.f;
            #pragma unroll 8
            for (int e = 0; e < DD; e++) a2 += sm_buf[e] * att_w1[e*DD + t];
            g_hsw1[b*DD + t] = a2;
        }
    }
}

// ---------------- fused front kernel (unchanged from R9) ---------------------------
#define FF_TMEM  0
#define FF_MBAR  8
#define FF_BIAS  64
#define FF_W2    2176
#define FF_ATTV  4288
#define FF_ALPHA 6400
#define FF_POSW1 8448
#define FF_AHID  34816
#define FF_ANH   100352
#define FF_B0    165888
#define FF_B1    198656
#define FF_SMEM  231424
#define IDESC64 ((1u<<4)|(1u<<7)|(1u<<10)|(8u<<17)|(8u<<24))

#if HAS_TCGEN05
__device__ __forceinline__ void f_load_chunk(uint32_t dst, const __nv_bfloat16* hi,
                                             const __nv_bfloat16* lo, int row0,
                                             int KD, int col0, int tid)
{
    #pragma unroll 8
    for (int i = tid; i < 2048; i += 256) {
        int half = i >> 10, rem = i & 1023;
        int r = rem >> 4, c8 = rem & 15;
        const __nv_bfloat16* src = (half ? lo : hi)
            + (size_t)(row0 + r)*KD + col0 + (c8 >> 3)*64 + (c8 & 7)*8;
        uint32_t byte = (uint32_t)((c8 >> 3)*8 + (r >> 3))*1024u
                      + (uint32_t)(r & 7)*128u + (uint32_t)(c8 & 7)*16u;
        cp16(dst + half*16384u + SWZ128(byte), src);
    }
    cp_commit();
}
__device__ __forceinline__ void f_mma_chunk(uint32_t d, uint32_t sbase,
                                            uint32_t aoff, uint32_t boff)
{
    uint64_t dAh = MAKE_DESC(sbase + aoff), dAl = MAKE_DESC(sbase + aoff + 32768);
    uint64_t dBh = MAKE_DESC(sbase + boff), dBl = MAKE_DESC(sbase + boff + 16384);
    uint64_t ad[3] = { dAh, dAh, dAl };
    uint64_t bd[3] = { dBh, dBl, dBh };
    #pragma unroll
    for (int p = 0; p < 3; p++)
        #pragma unroll
        for (int s = 0; s < 8; s++)
            mma_f16_ss(d, ad[p] + (uint64_t)((s >> 2)*1024 + (s & 3)*2),
                       bd[p] + (uint64_t)((s >> 2)*512 + (s & 3)*2),
                       IDESC64, !(p == 0 && s == 0));
}
#endif

__global__ void __launch_bounds__(256, 1) k_front(
    const float* __restrict__ hidden, const float* __restrict__ glu1_b,
    const float* __restrict__ w2, const float* __restrict__ att_v,
    const int* __restrict__ mask, const float* __restrict__ pos_emb,
    const float* __restrict__ w1)
{
#if HAS_TCGEN05
    extern __shared__ char smem[];
    uint32_t sbase = smem_u32(smem);
    int tid = threadIdx.x, wid = tid >> 5, lane = tid & 31;
    int mtile = blockIdx.x;
    uint32_t mbar = sbase + FF_MBAR;

    if (tid == 0)
        asm volatile("mbarrier.init.shared.b64 [%0], 1;" :: "r"(mbar) : "memory");
    if (wid == 0)
        asm volatile("tcgen05.alloc.cta_group::1.sync.aligned.shared::cta.b32 [%0], %1;"
                     :: "r"(sbase + FF_TMEM), "r"(512u) : "memory");
    __syncthreads();
    uint32_t tmem;
    asm volatile("ld.shared.b32 %0, [%1];" : "=r"(tmem) : "r"(sbase + FF_TMEM));

    f_load_chunk(sbase + FF_B0, g_w1b_hi, g_w1b_lo,  0, 256, 128, tid);
    f_load_chunk(sbase + FF_B1, g_w1b_hi, g_w1b_lo, 64, 256, 128, tid);

    for (int i = tid; i < 128*16; i += 256) {
        int r = i >> 4, c8 = i & 15;
        int m = mtile*128 + r;
        int col = (c8 >> 3)*64 + (c8 & 7)*8;
        const float* src = hidden + (size_t)m*DD + col;
        float f[8];
        *(float4*)f       = *(const float4*)src;
        *(float4*)(f + 4) = *(const float4*)(src + 4);
        __align__(16) ushort h[8], l[8];
        #pragma unroll
        for (int q = 0; q < 8; q++) { float rem; h[q] = bf_hi_us(f[q], rem); l[q] = bf_us(rem); }
        uint32_t byte = (uint32_t)((c8 >> 3)*16 + (r >> 3))*1024u
                      + (uint32_t)(r & 7)*128u + (uint32_t)(c8 & 7)*16u;
        uint32_t sw = SWZ128(byte);
        *(uint4*)(smem + FF_AHID + sw)         = *(uint4*)h;
        *(uint4*)(smem + FF_AHID + 32768 + sw) = *(uint4*)l;
    }
    {
        float* bias = (float*)(smem + FF_BIAS);
        float* w2s  = (float*)(smem + FF_W2);
        float* avs  = (float*)(smem + FF_ATTV);
        for (int i = tid; i < 512; i += 256) { bias[i] = glu1_b[i]; w2s[i] = w2[i]; avs[i] = att_v[i]; }
        float* pw = (float*)(smem + FF_POSW1);
        for (int i = tid; i < 50*128; i += 256) pw[(i >> 7)*129 + (i & 127)] = g_posw1[i];
    }
    cp_wait0();
    __syncthreads();

    if (wid == 0 && elect1()) {
        asm volatile("fence.proxy.async.shared::cta;" ::: "memory");
        f_mma_chunk(tmem +  0, sbase, FF_AHID, FF_B0);
        f_mma_chunk(tmem + 64, sbase, FF_AHID, FF_B1);
        TCOMMIT(mbar);
    }
    MBAR_WAIT(mbar, 0u);

    f_load_chunk(sbase + FF_B0, g_aw2b_hi, g_aw2b_lo,  0, 128, 0, tid);
    f_load_chunk(sbase + FF_B1, g_aw2b_hi, g_aw2b_lo, 64, 128, 0, tid);
    cp_wait0();
    __syncthreads();
    if (wid == 0 && elect1()) {
        asm volatile("fence.proxy.async.shared::cta;" ::: "memory");
        f_mma_chunk(tmem + 128, sbase, FF_AHID, FF_B0);
        f_mma_chunk(tmem + 192, sbase, FF_AHID, FF_B1);
        TCOMMIT(mbar);
    }
    MBAR_WAIT(mbar, 1u);
    asm volatile("tcgen05.fence::after_thread_sync;" ::: "memory");

    f_load_chunk(sbase + FF_B0, g_glub_hi, g_glub_lo,  0, 128, 0, tid);
    f_load_chunk(sbase + FF_B1, g_glub_hi, g_glub_lo, 64, 128, 0, tid);

    {
        int sub = wid & 3;
        int mloc = sub*32 + lane;
        int mglob = mtile*128 + mloc;
        if (wid < 4) {
            const float* prow = (const float*)(smem + FF_POSW1) + (mglob % LL)*129;
            #pragma unroll 1
            for (int ch = 0; ch < 4; ch++) {
                uint32_t r[32];
                LDTM32(r, tmem + ch*32);
                asm volatile("tcgen05.wait::ld.sync.aligned;" ::: "memory");
                #pragma unroll
                for (int q = 0; q < 4; q++) {
                    __align__(16) ushort h8[8], l8[8];
                    #pragma unroll
                    for (int u = 0; u < 8; u++) {
                        int c = ch*32 + q*8 + u;
                        float v = tanhf(__uint_as_float(r[q*8 + u]) + prow[c]);
                        float rem; h8[u] = bf_hi_us(v, rem); l8[u] = bf_us(rem);
                    }
                    int c8 = ch*4 + q;
                    uint32_t byte = (uint32_t)((c8 >> 3)*16 + (mloc >> 3))*1024u
                                  + (uint32_t)(mloc & 7)*128u + (uint32_t)(c8 & 7)*16u;
                    uint32_t sw = SWZ128(byte);
                    *(uint4*)(smem + FF_ANH + sw)         = *(uint4*)h8;
                    *(uint4*)(smem + FF_ANH + 32768 + sw) = *(uint4*)l8;
                }
            }
        } else {
            const float* hsrow = g_hsw1 + (mglob / LL)*DD;
            const float* avs = (const float*)(smem + FF_ATTV);
            float acc[4] = {};
            #pragma unroll 1
            for (int ch = 0; ch < 4; ch++) {
                uint32_t r[32];
                LDTM32(r, tmem + 128 + ch*32);
                asm volatile("tcgen05.wait::ld.sync.aligned;" ::: "memory");
                #pragma unroll
                for (int j = 0; j < 32; j++) {
                    int c = ch*32 + j;
                    float t = tanhf(__uint_as_float(r[j]) + hsrow[c]);
                    #pragma unroll
                    for (int k = 0; k < 4; k++) acc[k] += t * avs[c*4 + k];
                }
            }
            float* al = (float*)(smem + FF_ALPHA);
            #pragma unroll
            for (int k = 0; k < 4; k++) al[mloc*4 + k] = sigmoidf(acc[k]);
        }
        asm volatile("tcgen05.fence::before_thread_sync;" ::: "memory");
    }
    cp_wait0();
    __syncthreads();

    int ph = 0;
    for (int p = 0; p < 4; p++) {
        if (wid == 0 && elect1()) {
            asm volatile("tcgen05.fence::after_thread_sync;" ::: "memory");
            asm volatile("fence.proxy.async.shared::cta;" ::: "memory");
            f_mma_chunk(tmem + (2*p    )*64, sbase, FF_ANH, FF_B0);
            f_mma_chunk(tmem + (2*p + 1)*64, sbase, FF_ANH, FF_B1);
            TCOMMIT(mbar);
        }
        MBAR_WAIT(mbar, (uint32_t)(ph & 1));
        ph++;
        if (p < 3) {
            f_load_chunk(sbase + FF_B0, g_glub_hi, g_glub_lo, (2*p + 2)*64, 128, 0, tid);
            f_load_chunk(sbase + FF_B1, g_glub_hi, g_glub_lo, (2*p + 3)*64, 128, 0, tid);
            cp_wait0();
            __syncthreads();
        }
    }
    asm volatile("tcgen05.fence::after_thread_sync;" ::: "memory");

    {
        int sub = wid & 3, g = wid >> 2;
        int mloc = sub*32 + lane;
        int mglob = mtile*128 + mloc;
        const float* bias = (const float*)(smem + FF_BIAS);
        const float* w2s  = (const float*)(smem + FF_W2);
        float acc0 = 0.f, acc1 = 0.f;
        #pragma unroll 1
        for (int cc = 0; cc < 8; cc++) {
            int ch = g*8 + cc;
            uint32_t r[32];
            LDTM32(r, tmem + ch*32);
            asm volatile("tcgen05.wait::ld.sync.aligned;" ::: "memory");
            int k = ch >> 2;
            float a = 0.f;
            #pragma unroll
            for (int j = 0; j < 32; j++) {
                int n = ch*32 + j;
                float s = sigmoidf(__uint_as_float(r[j]) + bias[n]);
                a += s * w2s[(n & 127)*4 + k];
            }
            if (cc < 4) acc0 += a; else acc1 += a;
        }
        const float* al = (const float*)(smem + FF_ALPHA);
        float mk = (float)mask[mglob];
        float2 o;
        o.x = acc0 * (0.5f + al[mloc*4 + 2*g    ]) * mk;
        o.y = acc1 * (0.5f + al[mloc*4 + 2*g + 1]) * mk;
        *(float2*)(g_beta + mglob*4 + 2*g) = o;
    }
    __syncthreads();
    if (wid == 0)
        asm volatile("tcgen05.dealloc.cta_group::1.sync.aligned.b32 %0, %1;"
                     :: "r"(tmem), "r"(512u));
#else
    int tid = threadIdx.x;
    if (tid >= 128) return;
    int m = blockIdx.x*128 + tid;
    float nh[128];
    for (int n = 0; n < 128; n++) {
        float acc = 0.f;
        for (int k = 0; k < 128; k++) acc += pos_emb[(m % LL)*DD + k] * w1[k*128 + n];
        for (int k = 0; k < 128; k++) {
            float b = __bfloat162float(g_w1b_hi[n*256 + 128 + k]) + __bfloat162float(g_w1b_lo[n*256 + 128 + k]);
            acc += hidden[(size_t)m*DD + k] * b;
        }
        nh[n] = tanhf(acc);
    }
    float alpha[4] = {};
    for (int n = 0; n < 128; n++) {
        float x = 0.f;
        for (int k = 0; k < 128; k++)
            x += hidden[(size_t)m*DD + k] *
                 (__bfloat162float(g_aw2b_hi[n*128 + k]) + __bfloat162float(g_aw2b_lo[n*128 + k]));
        float t = tanhf(x + g_hsw1[(m / LL)*DD + n]);
        for (int k = 0; k < 4; k++) alpha[k] += t * att_v[n*4 + k];
    }
    for (int k = 0; k < 4; k++) alpha[k] = sigmoidf(alpha[k]);
    float acc[4] = {};
    for (int n = 0; n < 512; n++) {
        float x = 0.f;
        for (int k = 0; k < 128; k++)
            x += nh[k] * (__bfloat162float(g_glub_hi[n*128 + k]) + __bfloat162float(g_glub_lo[n*128 + k]));
        float s = sigmoidf(x + glu1_b[n]);
        acc[n >> 7] += s * w2[(n & 127)*4 + (n >> 7)];
    }
    float mk = (float)mask[m];
    for (int k = 0; k < 4; k++)
        g_beta[m*4 + k] = acc[k] * (0.5f + alpha[k]) * mk;
#endif
}

// ---------------- select (blocks 0..255, 2-way L split) + loss (block 256) ---------
__global__ void k_sel_loss(const float* __restrict__ hidden, float* __restrict__ out_scalar)
{
    __shared__ float part[2][DD][4];
    __shared__ float red[BB];
    int t = threadIdx.x;
    if (blockIdx.x < BB) {
        int b = blockIdx.x;
        int d = t & 127, lh = t >> 7;
        float acc[4] = {};
        #pragma unroll 5
        for (int l = lh*25; l < lh*25 + 25; l++) {
            float h = hidden[(size_t)(b*LL + l)*DD + d];
            float4 be = *(const float4*)(&g_beta[(b*LL + l)*4]);
            acc[0] += be.x*h; acc[1] += be.y*h; acc[2] += be.z*h; acc[3] += be.w*h;
        }
        #pragma unroll
        for (int k = 0; k < 4; k++) part[lh][d][k] = acc[k];
        __syncthreads();
        if (t < 128) {
            #pragma unroll
            for (int k = 0; k < 4; k++) {
                float v = part[0][t][k] + part[1][t][k];
                __nv_bfloat16 hi = __float2bfloat16(v);
                __nv_bfloat16 lo = __float2bfloat16(v - __bfloat162float(hi));
                g_sel_hi[(b*4 + k)*DD + t] = hi;
                g_sel_lo[(b*4 + k)*DD + t] = lo;
            }
        }
    } else {
        int b = t;
        float n2[4] = {};
        for (int l = 0; l < LL; l++) {
            float4 be = *(const float4*)(&g_beta[(b*LL + l)*4]);
            n2[0]+=be.x*be.x; n2[1]+=be.y*be.y; n2[2]+=be.z*be.z; n2[3]+=be.w*be.w;
        }
        float inv[4];
        #pragma unroll
        for (int k = 0; k < 4; k++) inv[k] = 1.0f / fmaxf(sqrtf(n2[k]), EPS_N);
        float G[6] = {};
        for (int l = 0; l < LL; l++) {
            float4 be = *(const float4*)(&g_beta[(b*LL + l)*4]);
            float v0=be.x*inv[0], v1=be.y*inv[1], v2=be.z*inv[2], v3=be.w*inv[3];
            G[0]+=v0*v1; G[1]+=v0*v2; G[2]+=v0*v3;
            G[3]+=v1*v2; G[4]+=v1*v3; G[5]+=v2*v3;
        }
        float sim = 0.f;
        #pragma unroll
        for (int i = 0; i < 6; i++) sim += fabsf(G[i]);
        sim *= (2.0f / (KK*(KK-1)));
        float lossb = sigmoidf(sim * g_lens[b]);
        red[b] = lossb;  __syncthreads();
        for (int s = BB/2; s > 0; s >>= 1) {
            if (b < s) red[b] += red[b + s];
            __syncthreads();
        }
        if (b == 0) *out_scalar = red[0] * BETA_S;
    }
}

// ---------------- scores: persistent CTAs, N=128 tiles, TS-mode MMA ----------------
// TMEM: D0 @0 (128), D1 @128 (128), A_hi @256 (64), A_lo @320 (64).
#define SC_TILES 391
#define SC_STRIDE 18
#define S_IDESC ((1u<<4) | (1u<<7) | (1u<<10) | ((128/8)<<17) | (8u<<24))
#define S2_TMEM  0
#define S2_MBAR0 8
#define S2_MBAR1 16
#define S2_B0    1024
#define S2_B1    (1024 + 65536)
#define S2_STG   (1024 + 131072)
#define S2_SMEM_TOT (132096 + 8*32*33*4)

#if HAS_TCGEN05
__device__ __forceinline__ void s2_load_b(uint32_t bufbase, int vtile, int tid)
{
    int vbase = vtile * 128;
    #pragma unroll 4
    for (int i = tid; i < 4096; i += 256) {
        int half = i >> 11, rem = i & 2047;
        int r = rem >> 4, c8 = rem & 15;
        int v = vbase + r; if (v > VM1 - 1) v = VM1 - 1;
        const __nv_bfloat16* src = (half ? g_emb_lo : g_emb_hi)
                                 + (size_t)v*DD + (c8 >> 3)*64 + (c8 & 7)*8;
        uint32_t byte = (uint32_t)((c8 >> 3)*16 + (r >> 3))*1024u
                      + (uint32_t)(r & 7)*128u + (uint32_t)(c8 & 7)*16u;
        cp16(bufbase + half*32768u + SWZ128(byte), src);
    }
    cp_commit();
}
__device__ __forceinline__ void s2_mma(uint32_t tmem, int dhalf, uint32_t sbase,
                                       uint32_t bufoff, uint32_t mbar)
{
    asm volatile("fence.proxy.async.shared::cta;" ::: "memory");
    uint64_t dBh = MAKE_DESC(sbase + bufoff);
    uint64_t dBl = MAKE_DESC(sbase + bufoff + 32768);
    uint32_t d  = tmem + (dhalf << 7);
    uint32_t aH = tmem + 256, aL = tmem + 320;
    uint32_t ap[3] = { aH, aH, aL };
    uint64_t bp[3] = { dBh, dBl, dBh };
    #pragma unroll
    for (int p = 0; p < 3; p++) {
        #pragma unroll
        for (int s = 0; s < 8; s++) {
            mma_f16_ts(d, ap[p] + s*8,
                       bp[p] + (uint64_t)((s >> 2)*1024 + (s & 3)*2),
                       S_IDESC, !(p == 0 && s == 0));
        }
    }
    asm volatile(
        "tcgen05.commit.cta_group::1.mbarrier::arrive::one.shared::cluster.b64 [%0];"
        :: "r"(mbar) : "memory");
}
#endif

__global__ void __launch_bounds__(256, 1) k_scores_mma(
        float* __restrict__ maxsc, float* __restrict__ scores)
{
#if HAS_TCGEN05
    extern __shared__ char smem[];
    uint32_t sbase = smem_u32(smem);
    int tid = threadIdx.x, wid = tid >> 5, lane = tid & 31;
    int mtile = blockIdx.x;
    int y = blockIdx.y;
    int nt = (SC_TILES - y + SC_STRIDE - 1) / SC_STRIDE;

    if (tid == 0) {
        asm volatile("mbarrier.init.shared.b64 [%0], 1;" :: "r"(sbase + S2_MBAR0) : "memory");
        asm volatile("mbarrier.init.shared.b64 [%0], 1;" :: "r"(sbase + S2_MBAR1) : "memory");
    }
    if (wid == 0)
        asm volatile("tcgen05.alloc.cta_group::1.sync.aligned.shared::cta.b32 [%0], %1;"
                     :: "r"(sbase + S2_TMEM), "r"(512u) : "memory");
    __syncthreads();
    uint32_t tmem;
    asm volatile("ld.shared.b32 %0, [%1];" : "=r"(tmem) : "r"(sbase + S2_TMEM));

    s2_load_b(sbase + S2_B0, y, tid);
    s2_load_b(sbase + S2_B1, y + SC_STRIDE, tid);
    if (tid < 128) {
        int m = mtile*128 + tid;
        const uint32_t* ph = (const uint32_t*)g_sel_hi + (size_t)m*64;
        const uint32_t* pl = (const uint32_t*)g_sel_lo + (size_t)m*64;
        uint32_t woff = (uint32_t)(tid >> 5) << 21;
        uint32_t a[32];
        #pragma unroll
        for (int q = 0; q < 32; q++) a[q] = ph[q];
        STTM32(tmem + 256 + woff, a);
        #pragma unroll
        for (int q = 0; q < 32; q++) a[q] = ph[32 + q];
        STTM32(tmem + 288 + woff, a);
        #pragma unroll
        for (int q = 0; q < 32; q++) a[q] = pl[q];
        STTM32(tmem + 320 + woff, a);
        #pragma unroll
        for (int q = 0; q < 32; q++) a[q] = pl[32 + q];
        STTM32(tmem + 352 + woff, a);
        asm volatile("tcgen05.wait::st.sync.aligned;" ::: "memory");
    }
    cp_wait1();
    __syncthreads();
    if (wid == 0 && elect1())
        s2_mma(tmem, 0, sbase, S2_B0, sbase + S2_MBAR0);

    int sub = wid & 3, h = wid >> 2;
    float* stg = (float*)(smem + S2_STG + wid*(32*33*4));
    size_t base_b0 = (size_t)(mtile*32 + sub*8) * VM1;
    const size_t KSTR = (size_t)BB * VM1;

    for (int i = 0; i < nt; i++) {
        cp_wait0();
        MBAR_WAIT(sbase + ((i & 1) ? S2_MBAR1 : S2_MBAR0), (uint32_t)((i >> 1) & 1));
        asm volatile("tcgen05.fence::after_thread_sync;" ::: "memory");
        __syncthreads();

        if (i + 1 < nt && wid == 0 && elect1())
            s2_mma(tmem, (i + 1) & 1, sbase,
                   ((i + 1) & 1) ? S2_B1 : S2_B0,
                   sbase + (((i + 1) & 1) ? S2_MBAR1 : S2_MBAR0));
        if (i + 2 < nt)
            s2_load_b(sbase + ((i & 1) ? S2_B1 : S2_B0), y + (i + 2)*SC_STRIDE, tid);

        uint32_t dbase = tmem + ((i & 1) << 7);
        int vb = (y + i*SC_STRIDE)*128;
        // paired LDTM: issue both chunks, single wait
        uint32_t r0[32], r1[32];
        LDTM32(r0, dbase + h*64);
        LDTM32(r1, dbase + h*64 + 32);
        asm volatile("tcgen05.wait::ld.sync.aligned;" ::: "memory");
        #pragma unroll 1
        for (int cc = 0; cc < 2; cc++) {
            int col0 = h*64 + cc*32;
            #pragma unroll
            for (int c = 0; c < 32; c++)
                stg[lane*33 + c] = __uint_as_float(cc ? r1[c] : r0[c]);
            __syncwarp();
            int v = vb + col0 + lane;
            bool ok = v < VM1;
            float* sc0 = scores + base_b0 + v;
            float* mx0 = maxsc + base_b0 + v;
            #pragma unroll
            for (int lb = 0; lb < 8; lb++) {
                float mx = -3.402823466e38f;
                #pragma unroll
                for (int j = 0; j < 4; j++) {
                    float x = stg[(lb*4 + j)*33 + lane];
                    if (ok) __stcs(sc0 + (size_t)lb*VM1 + (size_t)j*KSTR, x);
                    mx = fmaxf(mx, x);
                }
                if (ok) __stcs(mx0 + (size_t)lb*VM1, mx);
            }
            __syncwarp();
        }
    }
    __syncthreads();
    if (wid == 0)
        asm volatile("tcgen05.dealloc.cta_group::1.sync.aligned.b32 %0, %1;"
                     :: "r"(tmem), "r"(512u));
#else
    int tid = threadIdx.x;
    int mtile = blockIdx.x;
    int y = blockIdx.y;
    for (int vt = y; vt < SC_TILES; vt += SC_STRIDE) {
        int vbase = vt*128;
        for (int p = tid; p < 32*128; p += 256) {
            int bl = p >> 7, vv = vbase + (p & 127);
            if (vv >= VM1) continue;
            int b = mtile*32 + bl;
            float mx = -3.402823466e38f;
            for (int k = 0; k < 4; k++) {
                int m = (b*4 + k);
                float acc = 0.f;
                for (int d = 0; d < DD; d++) {
                    float a = __bfloat162float(g_sel_hi[m*DD + d]) + __bfloat162float(g_sel_lo[m*DD + d]);
                    float e = __bfloat162float(g_emb_hi[(size_t)vv*DD + d]) + __bfloat162float(g_emb_lo[(size_t)vv*DD + d]);
                    acc += a * e;
                }
                scores[((size_t)k*BB + b)*VM1 + vv] = acc;
                mx = fmaxf(mx, acc);
            }
            maxsc[(size_t)b*VM1 + vv] = mx;
        }
    }
#endif
}

// ---------------- launch ------------------------------------------------------------
extern "C" void kernel_launch(void* const* d_in, const int* in_sizes, int n_in,
                              void* d_out, int out_size)
{
    const float* hidden  = (const float*)d_in[0];
    const int*   mask    = (const int*)  d_in[1];
    const float* pos_emb = (const float*)d_in[2];
    const float* w1      = (const float*)d_in[3];
    const float* w2      = (const float*)d_in[4];
    const float* glu1_w  = (const float*)d_in[5];
    const float* glu1_b  = (const float*)d_in[6];
    const float* att_w1  = (const float*)d_in[7];
    const float* att_w2  = (const float*)d_in[8];
    const float* att_v   = (const float*)d_in[9];
    const float* emb     = (const float*)d_in[10];

    float* out    = (float*)d_out;
    float* maxsc  = out;                                   // [B, Vm1]
    float* scalar = out + (size_t)BB*VM1;                  // [1]
    float* scores = out + (size_t)BB*VM1 + 1;              // [K, B, Vm1]

    cudaFuncSetAttribute(k_scores_mma,
                         cudaFuncAttributeMaxDynamicSharedMemorySize, S2_SMEM_TOT);
    cudaFuncSetAttribute(k_front,
                         cudaFuncAttributeMaxDynamicSharedMemorySize, FF_SMEM);

    k_prep<<<PREP_GRID, 256>>>(emb, w1, glu1_w, att_w2, pos_emb, hidden, mask, att_w1);
    k_front<<<100, 256, FF_SMEM>>>(hidden, glu1_b, w2, att_v, mask, pos_emb, w1);
    k_sel_loss<<<BB + 1, 256>>>(hidden, scalar);
    k_scores_mma<<<dim3(8, SC_STRIDE), 256, S2_SMEM_TOT>>>(maxsc, scores);
}